// round 17
// baseline (speedup 1.0000x reference)
#include <cuda_runtime.h>
#include <math.h>

#define BV 32

// ---------------- weight scratch ----------------
__device__ __align__(16) float g_WqT[1024];
__device__ __align__(16) float g_WkT[1024];
__device__ __align__(16) float g_WvT[1024];
__device__ __align__(16) float g_Wn1T[64*256];    // [i][j]
__device__ __align__(16) float g_Wn2T[256*32];    // [j][d]
__device__ __align__(16) float g_CA[32*256];      // [d][j]
__device__ __align__(16) float g_CB[32*256];
__device__ __align__(16) float g_cbA[256];
__device__ __align__(16) float g_cbB[256];        // includes be1
__device__ __align__(16) float g_w65[256];

// ---------------- activation scratch ----------------
__device__ __align__(16) float g_q [9216*32];
__device__ __align__(16) float g_v [9216*32];
__device__ __align__(16) float g_kT[9216*32];     // per seg: [b][d][node]

__device__ __align__(16) float g_R1 [BV*32*32];
__device__ __align__(16) float g_R2 [BV*32*32];
__device__ __align__(16) float g_A1 [BV*32*256];
__device__ __align__(16) float g_A2 [BV*128*256];
__device__ __align__(16) float g_A3 [BV*32*256];
__device__ __align__(16) float g_B1t[BV*256*64];  // [b][t][node]
__device__ __align__(16) float g_B2t[BV*256*64];
__device__ __align__(16) float g_B3t[BV*256*128];
__device__ __align__(16) float g_yv1[BV*64*32];
__device__ __align__(16) float g_yv2[BV*64*32];
__device__ __align__(16) float g_yv3[BV*128*32];

// ============================================================================
// prep: weight transposes + edge-MLP folding + Wn2 transpose. grid 57.
// ============================================================================
__global__ void prep_kernel(const float* __restrict__ Wq, const float* __restrict__ bq,
                            const float* __restrict__ Wk, const float* __restrict__ bk,
                            const float* __restrict__ Wv, const float* __restrict__ Wn1,
                            const float* __restrict__ Wn2,
                            const float* __restrict__ We1, const float* __restrict__ be1) {
    int blk = blockIdx.x, t = threadIdx.x;
    if (blk < 32) {
        int d = blk, j = t;
        float a = 0.f, b2 = 0.f;
        #pragma unroll 8
        for (int i = 0; i < 32; i++) {
            a  += Wq[i*32 + d] * We1[j*65 + i];
            b2 += Wk[i*32 + d] * We1[j*65 + 32 + i];
        }
        g_CA[d*256 + j] = a;
        g_CB[d*256 + j] = b2;
    } else if (blk == 32) {
        for (int idx = t; idx < 1024; idx += 256) {
            int d = idx >> 5, dd = idx & 31;
            g_WqT[dd*32 + d] = Wq[idx];
            g_WkT[dd*32 + d] = Wk[idx];
            g_WvT[dd*32 + d] = Wv[idx];
        }
        float ca = 0.f, cb2 = 0.f;
        #pragma unroll 8
        for (int i = 0; i < 32; i++) {
            ca  += We1[t*65 + i]      * bq[i];
            cb2 += We1[t*65 + 32 + i] * bk[i];
        }
        g_cbA[t] = ca;
        g_cbB[t] = cb2 + be1[t];
        g_w65[t] = We1[t*65 + 64];
    } else if (blk < 49) {
        int base = (blk - 33) * 1024;
        for (int k = t; k < 1024; k += 256) {
            int idx = base + k;
            int j = idx >> 6, i = idx & 63;
            g_Wn1T[i*256 + j] = Wn1[idx];
        }
    } else {                              // Wn2T: 8 blocks x 1024
        int base = (blk - 49) * 1024;
        for (int k = t; k < 1024; k += 256) {
            int f = base + k;
            int j = f >> 5, d = f & 31;
            g_Wn2T[f] = Wn2[d*256 + j];
        }
    }
}

// ============================================================================
// qkv: warp per node, lane = d. grid 32*36, block 256 (8 nodes).
// ============================================================================
__global__ void __launch_bounds__(256) qkv_kernel(
        const float* __restrict__ robot, const float* __restrict__ frontier,
        const float* __restrict__ rh, const float* __restrict__ fh,
        const float* __restrict__ bq, const float* __restrict__ bk,
        const float* __restrict__ bv) {
    __shared__ float ks[32][9];
    int tid = threadIdx.x, w = tid >> 5, lane = tid & 31;
    int b = blockIdx.x / 36, c = blockIdx.x % 36;
    const float* x; int n, chunk, rowbase;
    if (c < 4)       { x = robot;    n = 32;  chunk = c;      rowbase = 0; }
    else if (c < 20) { x = frontier; n = 128; chunk = c - 4;  rowbase = 1024; }
    else if (c < 28) { x = rh;       n = 64;  chunk = c - 20; rowbase = 5120; }
    else             { x = fh;       n = 64;  chunk = c - 28; rowbase = 7168; }
    int node = chunk*8 + w;
    float xval = x[(b*n + node)*32 + lane];
    float q = bq[lane], k = bk[lane], v = bv[lane];
    #pragma unroll 8
    for (int dd = 0; dd < 32; dd++) {
        float xv = __shfl_sync(0xffffffffu, xval, dd);
        q = fmaf(xv, g_WqT[dd*32 + lane], q);
        k = fmaf(xv, g_WkT[dd*32 + lane], k);
        v = fmaf(xv, g_WvT[dd*32 + lane], v);
    }
    int grow = rowbase + b*n + node;
    g_q[grow*32 + lane] = q;
    g_v[grow*32 + lane] = v;
    ks[lane][w] = k;
    __syncthreads();
    int d = tid >> 3, nd = tid & 7;
    g_kT[rowbase*32 + b*32*n + d*n + chunk*8 + nd] = ks[d][nd];
}

// ============================================================================
// node MLP hidden (intra, 8 rows)
// ============================================================================
__device__ __forceinline__ void mlp8_hidden(const float (*csT)[8], float (*hs)[256],
        const float* __restrict__ bn1, int tid) {
    float h[8];
    float b = bn1[tid];
    #pragma unroll
    for (int r = 0; r < 8; r++) h[r] = b;
    #pragma unroll 8
    for (int i = 0; i < 64; i++) {
        float wv = g_Wn1T[i*256 + tid];
        float4 c0 = *(const float4*)&csT[i][0];
        float4 c1 = *(const float4*)&csT[i][4];
        h[0] = fmaf(wv, c0.x, h[0]); h[1] = fmaf(wv, c0.y, h[1]);
        h[2] = fmaf(wv, c0.z, h[2]); h[3] = fmaf(wv, c0.w, h[3]);
        h[4] = fmaf(wv, c1.x, h[4]); h[5] = fmaf(wv, c1.y, h[5]);
        h[6] = fmaf(wv, c1.z, h[6]); h[7] = fmaf(wv, c1.w, h[7]);
    }
    #pragma unroll
    for (int r = 0; r < 8; r++) hs[r][tid] = fmaxf(h[r], 0.f);
}

// ============================================================================
// Intra (unchanged from round 13): attention + coop MLP + tails.
// ============================================================================
template<int NMI, int MODE>
__device__ __forceinline__ void intra_body(
        const float* __restrict__ x, float* __restrict__ out,
        const float* __restrict__ bn1, const float* __restrict__ bn2,
        const float* __restrict__ bv,
        int b, int chunk, int rowbase,
        float (*qs)[32], float (*es)[128], float (*csT)[8], float (*hs)[256],
        float (*psum)[8][32],
        float* __restrict__ Aout, float* __restrict__ Bout, float* __restrict__ yvout) {
    constexpr int n = NMI*32;
    int tid = threadIdx.x, w = tid >> 5, lane = tid & 31;
    int row = chunk*8 + w;
    int grow = rowbase + b*n + row;
    qs[w][lane] = g_q[grow*32 + lane];
    float xpre = x[(b*n + row)*32 + lane];
    __syncwarp();

    const float* kTg = g_kT + rowbase*32 + b*32*n;
    float s[NMI];
    #pragma unroll
    for (int k = 0; k < NMI; k++) s[k] = 0.f;
    #pragma unroll 8
    for (int d = 0; d < 32; d++) {
        float qd = qs[w][d];
        if constexpr (NMI == 4) {
            float4 kv = *(const float4*)&kTg[d*n + lane*4];
            s[0] = fmaf(qd, kv.x, s[0]); s[1] = fmaf(qd, kv.y, s[1]);
            s[2] = fmaf(qd, kv.z, s[2]); s[3] = fmaf(qd, kv.w, s[3]);
        } else if constexpr (NMI == 2) {
            float2 kv = *(const float2*)&kTg[d*n + lane*2];
            s[0] = fmaf(qd, kv.x, s[0]); s[1] = fmaf(qd, kv.y, s[1]);
        } else {
            s[0] = fmaf(qd, kTg[d*n + lane], s[0]);
        }
    }
    float mx = s[0];
    #pragma unroll
    for (int k = 1; k < NMI; k++) mx = fmaxf(mx, s[k]);
    #pragma unroll
    for (int o = 16; o; o >>= 1) mx = fmaxf(mx, __shfl_xor_sync(0xffffffffu, mx, o));
    float sum = 0.f;
    #pragma unroll
    for (int k = 0; k < NMI; k++) { s[k] = __expf(s[k] - mx); sum += s[k]; }
    #pragma unroll
    for (int o = 16; o; o >>= 1) sum += __shfl_xor_sync(0xffffffffu, sum, o);
    float inv = 1.f / sum;
    if constexpr (NMI == 4) {
        *(float4*)&es[w][lane*4] = make_float4(s[0]*inv, s[1]*inv, s[2]*inv, s[3]*inv);
    } else if constexpr (NMI == 2) {
        *(float2*)&es[w][lane*2] = make_float2(s[0]*inv, s[1]*inv);
    } else {
        es[w][lane] = s[0]*inv;
    }
    __syncthreads();

    {
        constexpr int NM8 = n/8;
        int sp = w;
        const float* vg = g_v + (rowbase + b*n)*32;
        float agg[8];
        #pragma unroll
        for (int r = 0; r < 8; r++) agg[r] = 0.f;
        #pragma unroll
        for (int m4 = 0; m4 < NM8/4; m4++) {
            int m = sp*NM8 + m4*4;
            float vv0 = vg[(m+0)*32 + lane];
            float vv1 = vg[(m+1)*32 + lane];
            float vv2 = vg[(m+2)*32 + lane];
            float vv3 = vg[(m+3)*32 + lane];
            #pragma unroll
            for (int r = 0; r < 8; r++) {
                float4 e4 = *(const float4*)&es[r][m];
                agg[r] = fmaf(e4.x, vv0, fmaf(e4.y, vv1, fmaf(e4.z, vv2, fmaf(e4.w, vv3, agg[r]))));
            }
        }
        #pragma unroll
        for (int r = 0; r < 8; r++) psum[r][sp][lane] = agg[r];
    }
    __syncthreads();
    {
        float acc = 0.f;
        #pragma unroll
        for (int q = 0; q < 8; q++) acc += psum[w][q][lane];
        csT[lane][w] = xpre;
        csT[32 + lane][w] = acc;
    }
    __syncthreads();
    mlp8_hidden(csT, hs, bn1, tid);
    __syncthreads();

    {
        float po[8];
        #pragma unroll
        for (int r = 0; r < 8; r++) po[r] = 0.f;
        #pragma unroll 2
        for (int jj = 0; jj < 32; jj += 4) {
            int j = w*32 + jj;
            float wv0 = g_Wn2T[(j+0)*32 + lane];
            float wv1 = g_Wn2T[(j+1)*32 + lane];
            float wv2 = g_Wn2T[(j+2)*32 + lane];
            float wv3 = g_Wn2T[(j+3)*32 + lane];
            #pragma unroll
            for (int r = 0; r < 8; r++) {
                float4 hv = *(const float4*)&hs[r][j];
                po[r] = fmaf(hv.x, wv0, fmaf(hv.y, wv1, fmaf(hv.z, wv2, fmaf(hv.w, wv3, po[r]))));
            }
        }
        #pragma unroll
        for (int r = 0; r < 8; r++) psum[r][w][lane] = po[r];
    }
    __syncthreads();
    {
        float acc = bn2[lane];
        #pragma unroll
        for (int q = 0; q < 8; q++) acc += psum[w][q][lane];
        float res = csT[lane][w] + acc;
        out[(b*n + row)*32 + lane] = res;
        qs[w][lane] = res;
    }
    __syncthreads();

    {
        const float* C  = (MODE <= 1) ? g_CA  : g_CB;
        const float* cb = (MODE <= 1) ? g_cbA : g_cbB;
        float pa[8];
        float c0 = cb[tid];
        #pragma unroll
        for (int r = 0; r < 8; r++) pa[r] = c0;
        #pragma unroll 2
        for (int dd = 0; dd < 32; dd += 4) {
            float wv0 = C[(dd+0)*256 + tid];
            float wv1 = C[(dd+1)*256 + tid];
            float wv2 = C[(dd+2)*256 + tid];
            float wv3 = C[(dd+3)*256 + tid];
            #pragma unroll
            for (int r = 0; r < 8; r++) {
                float4 rv = *(const float4*)&qs[r][dd];
                pa[r] = fmaf(rv.x, wv0, fmaf(rv.y, wv1, fmaf(rv.z, wv2, fmaf(rv.w, wv3, pa[r]))));
            }
        }
        if constexpr (MODE <= 1) {
            #pragma unroll
            for (int r = 0; r < 8; r++)
                Aout[(b*n + chunk*8 + r)*256 + tid] = pa[r];
        } else {
            float* dst = Bout + b*256*n + tid*n + chunk*8;
            *(float4*)dst       = make_float4(pa[0], pa[1], pa[2], pa[3]);
            *(float4*)(dst + 4) = make_float4(pa[4], pa[5], pa[6], pa[7]);
            float v0 = bv[lane], v1 = 0.f;
            #pragma unroll 8
            for (int d = 0; d < 32; d += 2) {
                v0 = fmaf(qs[w][d],   g_WvT[d*32 + lane],     v0);
                v1 = fmaf(qs[w][d+1], g_WvT[(d+1)*32 + lane], v1);
            }
            yvout[(b*n + row)*32 + lane] = v0 + v1;
        }
    }
}

__global__ void __launch_bounds__(256) intra_kernel(
        const float* __restrict__ robot, const float* __restrict__ frontier,
        const float* __restrict__ rh, const float* __restrict__ fh,
        const float* __restrict__ bn1, const float* __restrict__ bn2,
        const float* __restrict__ bv,
        float* __restrict__ f_out, float* __restrict__ rh_out, float* __restrict__ fh_out) {
    __shared__ __align__(16) float qs[8][32];
    __shared__ __align__(16) float es[8][128];
    __shared__ __align__(16) float csT[64][8];
    __shared__ __align__(16) float hs[8][256];
    __shared__ __align__(16) float psum[8][8][32];
    int b = blockIdx.x / 36, c = blockIdx.x % 36;
    if (c < 4)
        intra_body<1,0>(robot, g_R1, bn1, bn2, bv, b, c, 0,
                        qs, es, csT, hs, psum, g_A1, nullptr, nullptr);
    else if (c < 20)
        intra_body<4,1>(frontier, f_out, bn1, bn2, bv, b, c-4, 1024,
                        qs, es, csT, hs, psum, g_A2, nullptr, nullptr);
    else if (c < 28)
        intra_body<2,2>(rh, rh_out, bn1, bn2, bv, b, c-20, 5120,
                        qs, es, csT, hs, psum, nullptr, g_B1t, g_yv1);
    else
        intra_body<2,3>(fh, fh_out, bn1, bn2, bv, b, c-28, 7168,
                        qs, es, csT, hs, psum, nullptr, g_B2t, g_yv2);
}

// ============================================================================
// Edge kernel: warp = t-chunk; each warp processes ALL ROWS rows. ROWS=8 for
// inter1/2 (R=2), ROWS=4 for inter3 (R=4) — per-block weights/syncs amortize
// over 2x rows vs round 13. Score loop uses float2 t-groups to bound regs.
// MODE: 0=inter1(xout, Atail) 1=inter2(Btail/yvtail) 2=inter3(xout + eout)
// ============================================================================
template<int R, int ROWS>
struct __align__(16) ESmem {
    float As[ROWS][256];
    float scp[ROWS][8][32*R];   // reused as psum[ROWS][8][32] after softmax
    float es[ROWS][32*R];
    float aggp[ROWS][8][32];
    float csT[64][ROWS];
    float hs[ROWS][256];
    float rs[ROWS][32];
    float w65s[256];
    float we2s[256];
};

template<int R, int ROWS, int MODE>
__device__ __forceinline__ void edge_run(
        ESmem<R,ROWS>* sm,
        const float* __restrict__ x, const float* __restrict__ dis,
        const float* __restrict__ A, const float* __restrict__ Bt,
        const float* __restrict__ yv,
        const float* __restrict__ bn1, const float* __restrict__ bn2,
        const float* __restrict__ bv, const float* __restrict__ We2,
        float* __restrict__ xout, float* __restrict__ eout,
        int Nx, int b, int i0,
        float* __restrict__ Atail, float* __restrict__ Btail,
        float* __restrict__ yvtail) {
    constexpr int Ny  = 32*R;
    constexpr int TCH = 32;
    constexpr int SEG = Ny/8;
    int tid = threadIdx.x, w = tid >> 5, lane = tid & 31;
    int sp = w;

    sm->w65s[tid] = g_w65[tid];
    sm->we2s[tid] = We2[tid];
    #pragma unroll
    for (int r = 0; r < ROWS; r++) {
        const float* Ar = A + (b*Nx + i0 + r)*256;
        sm->As[r][w*32 + lane] = Ar[w*32 + lane];
    }
    float xpre = (w < ROWS) ? x[(b*Nx + i0 + w)*32 + lane] : 0.f;
    __syncthreads();

    float dv[ROWS][R];
    #pragma unroll
    for (int r = 0; r < ROWS; r++) {
        const float* dr = dis + (b*Nx + i0 + r)*Ny;
        if constexpr (R == 4) {
            float4 t4 = *(const float4*)&dr[lane*4];
            dv[r][0]=t4.x; dv[r][1]=t4.y; dv[r][2]=t4.z; dv[r][3]=t4.w;
        } else {
            float2 t2 = *(const float2*)&dr[lane*2];
            dv[r][0]=t2.x; dv[r][1]=t2.y;
        }
    }
    float sc[ROWS][R];
    #pragma unroll
    for (int r = 0; r < ROWS; r++)
        #pragma unroll
        for (int k = 0; k < R; k++) sc[r][k] = 0.f;

    const float* Bb = Bt + (b*256 + sp*TCH)*Ny;
    #pragma unroll 4
    for (int tt = 0; tt < TCH; tt += 2) {
        int t = sp*TCH + tt;
        float2 w6 = *(const float2*)&sm->w65s[t];
        float2 w2 = *(const float2*)&sm->we2s[t];
        float2 av[ROWS];
        #pragma unroll
        for (int r = 0; r < ROWS; r++)
            av[r] = *(const float2*)&sm->As[r][t];
        #pragma unroll
        for (int u = 0; u < 2; u++) {
            float w6u = u ? w6.y : w6.x;
            float w2u = u ? w2.y : w2.x;
            if constexpr (R == 4) {
                float4 Bv = *(const float4*)&Bb[(tt+u)*Ny + lane*4];
                #pragma unroll
                for (int r = 0; r < ROWS; r++) {
                    float base = u ? av[r].y : av[r].x;
                    float hh;
                    hh = fmaf(w6u, dv[r][0], base + Bv.x); sc[r][0] = fmaf(w2u, fmaxf(hh, 0.f), sc[r][0]);
                    hh = fmaf(w6u, dv[r][1], base + Bv.y); sc[r][1] = fmaf(w2u, fmaxf(hh, 0.f), sc[r][1]);
                    hh = fmaf(w6u, dv[r][2], base + Bv.z); sc[r][2] = fmaf(w2u, fmaxf(hh, 0.f), sc[r][2]);
                    hh = fmaf(w6u, dv[r][3], base + Bv.w); sc[r][3] = fmaf(w2u, fmaxf(hh, 0.f), sc[r][3]);
                }
            } else {
                float2 Bv = *(const float2*)&Bb[(tt+u)*Ny + lane*2];
                #pragma unroll
                for (int r = 0; r < ROWS; r++) {
                    float base = u ? av[r].y : av[r].x;
                    float hh;
                    hh = fmaf(w6u, dv[r][0], base + Bv.x); sc[r][0] = fmaf(w2u, fmaxf(hh, 0.f), sc[r][0]);
                    hh = fmaf(w6u, dv[r][1], base + Bv.y); sc[r][1] = fmaf(w2u, fmaxf(hh, 0.f), sc[r][1]);
                }
            }
        }
    }
    #pragma unroll
    for (int r = 0; r < ROWS; r++) {
        if constexpr (R == 4) {
            *(float4*)&sm->scp[r][sp][lane*4] = make_float4(sc[r][0], sc[r][1], sc[r][2], sc[r][3]);
        } else {
            *(float2*)&sm->scp[r][sp][lane*2] = make_float2(sc[r][0], sc[r][1]);
        }
    }
    __syncthreads();

    if (w < ROWS) {
        int i = i0 + w;
        float s[R];
        #pragma unroll
        for (int k = 0; k < R; k++) {
            float acc = 0.f;
            #pragma unroll
            for (int q = 0; q < 8; q++) acc += sm->scp[w][q][lane*R + k];
            s[k] = acc;
        }
        float mx = s[0];
        #pragma unroll
        for (int k = 1; k < R; k++) mx = fmaxf(mx, s[k]);
        #pragma unroll
        for (int o = 16; o; o >>= 1) mx = fmaxf(mx, __shfl_xor_sync(0xffffffffu, mx, o));
        float sum = 0.f;
        #pragma unroll
        for (int k = 0; k < R; k++) { s[k] = __expf(s[k] - mx); sum += s[k]; }
        #pragma unroll
        for (int o = 16; o; o >>= 1) sum += __shfl_xor_sync(0xffffffffu, sum, o);
        float inv = 1.f / sum;
        if constexpr (R == 4) {
            float4 p = make_float4(s[0]*inv, s[1]*inv, s[2]*inv, s[3]*inv);
            *(float4*)&sm->es[w][lane*4] = p;
            if (MODE == 2) *(float4*)&eout[(b*Nx + i)*Ny + lane*4] = p;
        } else {
            *(float2*)&sm->es[w][lane*2] = make_float2(s[0]*inv, s[1]*inv);
        }
    }
    __syncthreads();

    {
        const float* yvb = yv + (b*Ny + sp*SEG)*32;
        float agg[ROWS];
        #pragma unroll
        for (int r = 0; r < ROWS; r++) agg[r] = 0.f;
        #pragma unroll 4
        for (int m = 0; m < SEG; m++) {
            float vv = yvb[m*32 + lane];
            #pragma unroll
            for (int r = 0; r < ROWS; r++)
                agg[r] = fmaf(sm->es[r][sp*SEG + m], vv, agg[r]);
        }
        #pragma unroll
        for (int r = 0; r < ROWS; r++) sm->aggp[r][sp][lane] = agg[r];
    }
    __syncthreads();
    if (w < ROWS) {
        float acc = 0.f;
        #pragma unroll
        for (int q = 0; q < 8; q++) acc += sm->aggp[w][q][lane];
        sm->csT[lane][w] = xpre;
        sm->csT[32 + lane][w] = acc;
    }
    __syncthreads();

    // hidden layer: thread j covers all rows
    {
        float h[ROWS];
        float bb = bn1[tid];
        #pragma unroll
        for (int r = 0; r < ROWS; r++) h[r] = bb;
        #pragma unroll 8
        for (int i2 = 0; i2 < 64; i2++) {
            float wv = g_Wn1T[i2*256 + tid];
            if constexpr (ROWS == 8) {
                float4 c0 = *(const float4*)&sm->csT[i2][0];
                float4 c1 = *(const float4*)&sm->csT[i2][4];
                h[0] = fmaf(wv, c0.x, h[0]); h[1] = fmaf(wv, c0.y, h[1]);
                h[2] = fmaf(wv, c0.z, h[2]); h[3] = fmaf(wv, c0.w, h[3]);
                h[4] = fmaf(wv, c1.x, h[4]); h[5] = fmaf(wv, c1.y, h[5]);
                h[6] = fmaf(wv, c1.z, h[6]); h[7] = fmaf(wv, c1.w, h[7]);
            } else {
                float4 c0 = *(const float4*)&sm->csT[i2][0];
                h[0] = fmaf(wv, c0.x, h[0]); h[1] = fmaf(wv, c0.y, h[1]);
                h[2] = fmaf(wv, c0.z, h[2]); h[3] = fmaf(wv, c0.w, h[3]);
            }
        }
        #pragma unroll
        for (int r = 0; r < ROWS; r++) sm->hs[r][tid] = fmaxf(h[r], 0.f);
    }
    __syncthreads();

    // out layer, j-split (psum overlays scp)
    float* psum = &sm->scp[0][0][0];
    {
        float po[ROWS];
        #pragma unroll
        for (int r = 0; r < ROWS; r++) po[r] = 0.f;
        #pragma unroll 2
        for (int jj = 0; jj < 32; jj += 4) {
            int j = w*32 + jj;
            float wv0 = g_Wn2T[(j+0)*32 + lane];
            float wv1 = g_Wn2T[(j+1)*32 + lane];
            float wv2 = g_Wn2T[(j+2)*32 + lane];
            float wv3 = g_Wn2T[(j+3)*32 + lane];
            #pragma unroll
            for (int r = 0; r < ROWS; r++) {
                float4 hv = *(const float4*)&sm->hs[r][j];
                po[r] = fmaf(hv.x, wv0, fmaf(hv.y, wv1, fmaf(hv.z, wv2, fmaf(hv.w, wv3, po[r]))));
            }
        }
        #pragma unroll
        for (int r = 0; r < ROWS; r++) psum[(r*8 + w)*32 + lane] = po[r];
    }
    __syncthreads();
    if (w < ROWS) {
        int ii = i0 + w;
        float acc = bn2[lane];
        #pragma unroll
        for (int q = 0; q < 8; q++) acc += psum[(w*8 + q)*32 + lane];
        float res = sm->csT[lane][w] + acc;
        if (MODE == 0 || MODE == 2) xout[(b*Nx + ii)*32 + lane] = res;
        sm->rs[w][lane] = res;
    }
    __syncthreads();

    // projection tails, j-parallel
    if constexpr (MODE == 0 || MODE == 1) {
        const float* C  = (MODE == 0) ? g_CA  : g_CB;
        const float* cb = (MODE == 0) ? g_cbA : g_cbB;
        float pa[ROWS];
        float c0 = cb[tid];
        #pragma unroll
        for (int r = 0; r < ROWS; r++) pa[r] = c0;
        #pragma unroll 2
        for (int dd = 0; dd < 32; dd += 4) {
            float wv0 = C[(dd+0)*256 + tid];
            float wv1 = C[(dd+1)*256 + tid];
            float wv2 = C[(dd+2)*256 + tid];
            float wv3 = C[(dd+3)*256 + tid];
            #pragma unroll
            for (int r = 0; r < ROWS; r++) {
                float4 rv = *(const float4*)&sm->rs[r][dd];
                pa[r] = fmaf(rv.x, wv0, fmaf(rv.y, wv1, fmaf(rv.z, wv2, fmaf(rv.w, wv3, pa[r]))));
            }
        }
        if constexpr (MODE == 0) {
            #pragma unroll
            for (int r = 0; r < ROWS; r++)
                Atail[(b*Nx + i0 + r)*256 + tid] = pa[r];
        } else {
            static_assert(MODE != 1 || ROWS == 8, "MODE 1 expects ROWS==8");
            float* dst = Btail + b*256*128 + tid*128 + i0;
            *(float4*)dst       = make_float4(pa[0], pa[1], pa[2], pa[3]);
            *(float4*)(dst + 4) = make_float4(pa[4], pa[5], pa[6], pa[7]);
            if (w < ROWS) {
                int ii = i0 + w;
                float v0 = bv[lane], v1 = 0.f;
                #pragma unroll 8
                for (int d = 0; d < 32; d += 2) {
                    v0 = fmaf(sm->rs[w][d],   g_WvT[d*32 + lane],     v0);
                    v1 = fmaf(sm->rs[w][d+1], g_WvT[(d+1)*32 + lane], v1);
                }
                yvtail[(b*Nx + ii)*32 + lane] = v0 + v1;
            }
        }
    }
}

// inter1 (128 blocks, 8 rows each) + inter2 (512 blocks). grid 640, block 256.
__global__ void __launch_bounds__(256, 3) edge12_kernel(
        const float* __restrict__ f_in, const float* __restrict__ rp,
        const float* __restrict__ fpd,
        const float* __restrict__ bn1, const float* __restrict__ bn2,
        const float* __restrict__ We2, const float* __restrict__ bv) {
    __shared__ __align__(16) ESmem<2,8> sm;
    int blk = blockIdx.x;
    if (blk < 128) {
        int b = blk >> 2, i0 = (blk & 3)*8;
        edge_run<2,8,0>(&sm, g_R1, rp, g_A1, g_B1t, g_yv1, bn1, bn2, bv, We2,
                        g_R2, nullptr, 32, b, i0, g_A3, nullptr, nullptr);
    } else {
        blk -= 128;
        int b = blk >> 4, i0 = (blk & 15)*8;
        edge_run<2,8,1>(&sm, f_in, fpd, g_A2, g_B2t, g_yv2, bn1, bn2, bv, We2,
                        nullptr, nullptr, 128, b, i0, nullptr, g_B3t, g_yv3);
    }
}

// inter3: robot <- new_frontier. grid 256, block 256 (4 rows x 8 t-chunks).
__global__ void __launch_bounds__(256, 3) edge3_kernel(
        const float* __restrict__ rf,
        const float* __restrict__ bn1, const float* __restrict__ bn2,
        const float* __restrict__ We2, const float* __restrict__ bv,
        float* __restrict__ r_out, float* __restrict__ e_out) {
    __shared__ __align__(16) ESmem<4,4> sm;
    int b = blockIdx.x >> 3, i0 = (blockIdx.x & 7)*4;
    edge_run<4,4,2>(&sm, g_R2, rf, g_A3, g_B3t, g_yv3, bn1, bn2, bv, We2,
                    r_out, e_out, 32, b, i0, nullptr, nullptr, nullptr);
}

// ============================================================================
extern "C" void kernel_launch(void* const* d_in, const int* in_sizes, int n_in,
                              void* d_out, int out_size) {
    const float* robot    = (const float*)d_in[0];
    const float* frontier = (const float*)d_in[1];
    const float* rh       = (const float*)d_in[2];
    const float* fh       = (const float*)d_in[3];
    const float* rf       = (const float*)d_in[4];
    const float* rp       = (const float*)d_in[5];
    const float* fpd      = (const float*)d_in[6];
    const float* Wq  = (const float*)d_in[7];  const float* bq  = (const float*)d_in[8];
    const float* Wk  = (const float*)d_in[9];  const float* bk  = (const float*)d_in[10];
    const float* Wv  = (const float*)d_in[11]; const float* bv  = (const float*)d_in[12];
    const float* Wn1 = (const float*)d_in[13]; const float* bn1 = (const float*)d_in[14];
    const float* Wn2 = (const float*)d_in[15]; const float* bn2 = (const float*)d_in[16];
    const float* We1 = (const float*)d_in[17]; const float* be1 = (const float*)d_in[18];
    const float* We2 = (const float*)d_in[19];
    // d_in[20] = be2: softmax-invariant, unused.

    float* out    = (float*)d_out;
    float* r_out  = out;
    float* f_out  = r_out  + 32*32*32;
    float* rh_out = f_out  + 32*128*32;
    float* fh_out = rh_out + 32*64*32;
    float* e_out  = fh_out + 32*64*32;

    prep_kernel<<<57, 256>>>(Wq, bq, Wk, bk, Wv, Wn1, Wn2, We1, be1);
    qkv_kernel<<<32*36, 256>>>(robot, frontier, rh, fh, bq, bk, bv);
    intra_kernel<<<32*36, 256>>>(robot, frontier, rh, fh, bn1, bn2, bv,
                                 f_out, rh_out, fh_out);
    edge12_kernel<<<640, 256>>>(f_out, rp, fpd, bn1, bn2, We2, bv);
    edge3_kernel<<<256, 256>>>(rf, bn1, bn2, We2, bv, r_out, e_out);
}